// round 10
// baseline (speedup 1.0000x reference)
#include <cuda_runtime.h>
#include <cuda_fp16.h>
#include <math.h>
#include <stdint.h>

#define N 8192
#define D 256
#define K3 256                 // fp16-quantized embedding, exact dist on quantized vecs
#define TM 128
#define TN 128
#define NTB (N / TM)           // 64
#define NTILES (NTB * (NTB + 1) / 2)   // 2080
#define KC 64                  // k-elems per chunk = 128B rows
#define NC (K3 / KC)           // 4
#define MARGIN 0.3f
#define POS_INF_BITS 0x7f800000

// 3-stage smem: stage = A(16KB) + B(16KB)
#define STAGE_BYTES 32768
#define OFF_STAT (3 * STAGE_BYTES)     // 98304
#define STAT_BYTES 4096
#define SMEM_BYTES (OFF_STAT + STAT_BYTES + 1024)

// -------- device scratch --------
__device__ __half g_F[(size_t)N * K3];   // fp16-quantized normalized features
__device__ float g_sq[N];                // exact ||f_hat||^2 in fp32
__device__ int   g_lab[N];
__device__ int   g_maxpos[N];   // d2 float bits (>=0 -> monotone as int); sqrt deferred
__device__ int   g_minneg[N];
__device__ float g_part[64];
__device__ int   g_cnt;

// -------- helpers --------
__device__ __forceinline__ uint32_t smem_u32(const void* p) {
    return (uint32_t)__cvta_generic_to_shared(p);
}
__device__ __forceinline__ uint32_t swz(int row, int g) {   // 128B rows, 16B groups
    return (uint32_t)(row * 128 + ((g ^ (row & 7)) << 4));
}
__device__ __forceinline__ void cp16(uint32_t saddr, const void* gaddr) {
    asm volatile("cp.async.cg.shared.global [%0], [%1], 16;"
                 :: "r"(saddr), "l"(gaddr) : "memory");
}
__device__ __forceinline__ void ldsm4(uint32_t& r0, uint32_t& r1, uint32_t& r2,
                                      uint32_t& r3, uint32_t addr) {
    asm volatile("ldmatrix.sync.aligned.m8n8.x4.shared.b16 {%0,%1,%2,%3}, [%4];"
                 : "=r"(r0), "=r"(r1), "=r"(r2), "=r"(r3) : "r"(addr));
}
__device__ __forceinline__ void mma16816(float* d, const uint32_t* a, const uint32_t* b) {
    asm volatile(
        "mma.sync.aligned.m16n8k16.row.col.f32.f16.f16.f32 "
        "{%0,%1,%2,%3}, {%4,%5,%6,%7}, {%8,%9}, {%0,%1,%2,%3};"
        : "+f"(d[0]), "+f"(d[1]), "+f"(d[2]), "+f"(d[3])
        : "r"(a[0]), "r"(a[1]), "r"(a[2]), "r"(a[3]), "r"(b[0]), "r"(b[1]));
}

// -------- 1) label detect/convert + stats init, 32 blocks --------
// Every block independently samples the SAME first 128 odd 32-bit words to
// decide int64 vs int32 (deterministic; all blocks agree), then converts its
// own slice of 256 labels and inits the per-row stats.
__global__ void labels_kernel(const void* __restrict__ labels_raw) {
    const int* w = (const int*)labels_raw;
    int tid = threadIdx.x;   // 256 threads, 32 blocks
    if (blockIdx.x == 0 && tid == 0) g_cnt = 0;
    unsigned nz = 0;
    if (tid < 128) nz = (w[2 * tid + 1] != 0) ? 1u : 0u;
    nz = __ballot_sync(0xffffffffu, nz != 0);
    __shared__ unsigned s_nz[8];
    int wid = tid >> 5, lid = tid & 31;
    if (lid == 0) s_nz[wid] = nz;
    __syncthreads();
    bool is64 = ((s_nz[0] | s_nz[1] | s_nz[2] | s_nz[3]) == 0);  // warps 0-3 cover tid<128
    int i = blockIdx.x * 256 + tid;
    g_lab[i] = is64 ? w[2 * i] : w[i];
    g_maxpos[i] = 0;
    g_minneg[i] = POS_INF_BITS;
}

// -------- 2) normalize + quantize, warp-per-row (no block sync) --------
__global__ void normalize_convert_kernel(const float* __restrict__ f) {
    int wid = threadIdx.x >> 5, lane = threadIdx.x & 31;
    int row = blockIdx.x * 8 + wid;              // 1024 blocks x 8 warps
    const float4* fp = (const float4*)(f + (size_t)row * D);
    float4 v0 = fp[lane];          // elems [lane*4, lane*4+4)
    float4 v1 = fp[lane + 32];     // elems [128+lane*4, ...)
    float ss = v0.x * v0.x + v0.y * v0.y + v0.z * v0.z + v0.w * v0.w
             + v1.x * v1.x + v1.y * v1.y + v1.z * v1.z + v1.w * v1.w;
    #pragma unroll
    for (int o = 16; o > 0; o >>= 1) ss += __shfl_xor_sync(0xffffffffu, ss, o);
    float inv = 1.0f / fmaxf(sqrtf(ss), 1e-12f);

    __half h0 = __float2half_rn(v0.x * inv), h1 = __float2half_rn(v0.y * inv);
    __half h2 = __float2half_rn(v0.z * inv), h3 = __float2half_rn(v0.w * inv);
    __half h4 = __float2half_rn(v1.x * inv), h5 = __float2half_rn(v1.y * inv);
    __half h6 = __float2half_rn(v1.z * inv), h7 = __float2half_rn(v1.w * inv);

    __half2* out = (__half2*)(g_F + (size_t)row * K3);
    out[lane * 2]          = __halves2half2(h0, h1);
    out[lane * 2 + 1]      = __halves2half2(h2, h3);
    out[64 + lane * 2]     = __halves2half2(h4, h5);
    out[64 + lane * 2 + 1] = __halves2half2(h6, h7);

    // exact squared norm of the QUANTIZED vector
    float q0 = __half2float(h0), q1 = __half2float(h1), q2 = __half2float(h2),
          q3 = __half2float(h3), q4 = __half2float(h4), q5 = __half2float(h5),
          q6 = __half2float(h6), q7 = __half2float(h7);
    float s2 = q0 * q0 + q1 * q1 + q2 * q2 + q3 * q3
             + q4 * q4 + q5 * q5 + q6 * q6 + q7 * q7;
    #pragma unroll
    for (int o = 16; o > 0; o >>= 1) s2 += __shfl_xor_sync(0xffffffffu, s2, o);
    if (lane == 0) g_sq[row] = s2;
}

// -------- cp.async issue of one k-chunk into one smem stage --------
__device__ __forceinline__ void issue_chunk(uint32_t sb, int gi0, int gj0,
                                            int c, int tid) {
    uint32_t stage = sb + (uint32_t)(c % 3) * STAGE_BYTES;
    #pragma unroll
    for (int l = 0; l < 4; l++) {
        int idx = tid + l * 256;
        int row = idx >> 3, g = idx & 7;
        cp16(stage + swz(row, g),
             g_F + (size_t)(gi0 + row) * K3 + c * KC + g * 8);
        cp16(stage + 16384u + swz(row, g),
             g_F + (size_t)(gj0 + row) * K3 + c * KC + g * 8);
    }
}

// -------- 3) HMMA gram + fused epilogue (d2-space max/min), triangular grid ----
__global__ void __launch_bounds__(256, 2) tile_kernel() {
    // linear index -> (bi, bj) with bj >= bi
    int t = blockIdx.x;
    int p = (int)((sqrtf(8.0f * (float)t + 1.0f) - 1.0f) * 0.5f);
    while ((p + 1) * (p + 2) / 2 <= t) p++;
    while (p * (p + 1) / 2 > t) p--;
    int bi = t - p * (p + 1) / 2;
    int bj = p;

    extern __shared__ __align__(128) char dsm[];
    uint32_t raw = smem_u32(dsm);
    uint32_t sb = (raw + 1023) & ~1023u;
    char* base = dsm + (sb - raw);

    int*   lab_i_s = (int*)(base + OFF_STAT);
    float* sq_i_s  = (float*)(base + OFF_STAT + 512);
    int*   lab_j_s = (int*)(base + OFF_STAT + 1024);
    float* sq_j_s  = (float*)(base + OFF_STAT + 1536);
    int*   smax_i  = (int*)(base + OFF_STAT + 2048);
    int*   smin_i  = (int*)(base + OFF_STAT + 2560);
    int*   smax_j  = (int*)(base + OFF_STAT + 3072);
    int*   smin_j  = (int*)(base + OFF_STAT + 3584);

    int tid = threadIdx.x;
    int wid = tid >> 5, lane = tid & 31;
    int wr = wid & 3, wc = wid >> 2;          // 4x2 warp grid: 32 rows x 64 cols
    int gi0 = bi * TM, gj0 = bj * TN;

    // prologue: chunks 0 and 1 into stages 0,1
    issue_chunk(sb, gi0, gj0, 0, tid);
    asm volatile("cp.async.commit_group;" ::: "memory");
    issue_chunk(sb, gi0, gj0, 1, tid);
    asm volatile("cp.async.commit_group;" ::: "memory");

    if (tid < 128) {
        lab_i_s[tid] = g_lab[gi0 + tid];
        sq_i_s[tid]  = g_sq[gi0 + tid];
        lab_j_s[tid] = g_lab[gj0 + tid];
        sq_j_s[tid]  = g_sq[gj0 + tid];
        smax_i[tid] = 0; smin_i[tid] = POS_INF_BITS;
        smax_j[tid] = 0; smin_j[tid] = POS_INF_BITS;
    }

    float d[16][4];
    #pragma unroll
    for (int q = 0; q < 16; q++)
        #pragma unroll
        for (int r = 0; r < 4; r++) d[q][r] = 0.0f;

    // ldmatrix lane addressing
    int a_row = wr * 32 + ((lane >> 3) & 1) * 8 + (lane & 7);   // + mt*16
    int a_gh  = lane >> 4;
    int b_row = wc * 64 + ((lane >> 4) & 1) * 8 + (lane & 7);   // + p*16
    int b_gh  = (lane >> 3) & 1;

    uint32_t afr[2][8], bfr[2][16];

    for (int c = 0; c < NC; c++) {
        asm volatile("cp.async.wait_group 1;" ::: "memory");
        __syncthreads();
        if (c + 2 < NC) issue_chunk(sb, gi0, gj0, c + 2, tid);
        asm volatile("cp.async.commit_group;" ::: "memory");

        uint32_t abase = sb + (uint32_t)(c % 3) * STAGE_BYTES;
        uint32_t bbase = abase + 16384u;

        // preload kk=0 fragments
        ldsm4(afr[0][0], afr[0][1], afr[0][2], afr[0][3], abase + swz(a_row,      a_gh));
        ldsm4(afr[0][4], afr[0][5], afr[0][6], afr[0][7], abase + swz(a_row + 16, a_gh));
        #pragma unroll
        for (int pp = 0; pp < 4; pp++)
            ldsm4(bfr[0][4 * pp], bfr[0][4 * pp + 1], bfr[0][4 * pp + 2], bfr[0][4 * pp + 3],
                  bbase + swz(b_row + pp * 16, b_gh));

        #pragma unroll
        for (int kk = 0; kk < 4; kk++) {
            int cur = kk & 1, nxt = cur ^ 1;
            if (kk < 3) {   // prefetch kk+1 fragments before consuming kk
                ldsm4(afr[nxt][0], afr[nxt][1], afr[nxt][2], afr[nxt][3],
                      abase + swz(a_row,      (kk + 1) * 2 + a_gh));
                ldsm4(afr[nxt][4], afr[nxt][5], afr[nxt][6], afr[nxt][7],
                      abase + swz(a_row + 16, (kk + 1) * 2 + a_gh));
                #pragma unroll
                for (int pp = 0; pp < 4; pp++)
                    ldsm4(bfr[nxt][4 * pp], bfr[nxt][4 * pp + 1],
                          bfr[nxt][4 * pp + 2], bfr[nxt][4 * pp + 3],
                          bbase + swz(b_row + pp * 16, (kk + 1) * 2 + b_gh));
            }
            #pragma unroll
            for (int mt = 0; mt < 2; mt++)
                #pragma unroll
                for (int nt = 0; nt < 8; nt++)
                    mma16816(d[mt * 8 + nt], &afr[cur][mt * 4], &bfr[cur][nt * 2]);
        }
    }

    // ---- epilogue: masked max/min on d2 (sqrt deferred; monotone) ----
    float rmx[4], rmn[4], si[4];
    int li[4];
    #pragma unroll
    for (int mt = 0; mt < 2; mt++)
        #pragma unroll
        for (int h = 0; h < 2; h++) {
            int row = wr * 32 + mt * 16 + h * 8 + (lane >> 2);
            li[mt * 2 + h] = lab_i_s[row];
            si[mt * 2 + h] = sq_i_s[row];
            rmx[mt * 2 + h] = 0.0f;
            rmn[mt * 2 + h] = __int_as_float(POS_INF_BITS);
        }

    #pragma unroll
    for (int nt = 0; nt < 8; nt++) {
        #pragma unroll
        for (int cc = 0; cc < 2; cc++) {
            int col = wc * 64 + nt * 8 + (lane & 3) * 2 + cc;
            int lj = lab_j_s[col];
            float sj = sq_j_s[col];
            float pmax = 0.0f, nmin = __int_as_float(POS_INF_BITS);
            #pragma unroll
            for (int mt = 0; mt < 2; mt++)
                #pragma unroll
                for (int h = 0; h < 2; h++) {
                    float g = d[mt * 8 + nt][h * 2 + cc];
                    float d2 = fmaxf(si[mt * 2 + h] + sj - 2.0f * g, 1e-12f);
                    if (li[mt * 2 + h] == lj) {
                        rmx[mt * 2 + h] = fmaxf(rmx[mt * 2 + h], d2);
                        pmax = fmaxf(pmax, d2);
                    } else {
                        rmn[mt * 2 + h] = fminf(rmn[mt * 2 + h], d2);
                        nmin = fminf(nmin, d2);
                    }
                }
            unsigned pm = __float_as_uint(pmax), nm = __float_as_uint(nmin);
            #pragma unroll
            for (int o = 4; o <= 16; o <<= 1) {
                unsigned pp = __shfl_xor_sync(0xffffffffu, pm, o);
                unsigned nn = __shfl_xor_sync(0xffffffffu, nm, o);
                pm = pm > pp ? pm : pp;
                nm = nm < nn ? nm : nn;
            }
            if ((lane >> 2) == 0) {
                atomicMax(&smax_j[col], (int)pm);
                atomicMin(&smin_j[col], (int)nm);
            }
        }
    }
    #pragma unroll
    for (int r4 = 0; r4 < 4; r4++) {
        unsigned pm = __float_as_uint(rmx[r4]), nm = __float_as_uint(rmn[r4]);
        #pragma unroll
        for (int o = 1; o <= 2; o <<= 1) {
            unsigned pp = __shfl_xor_sync(0xffffffffu, pm, o);
            unsigned nn = __shfl_xor_sync(0xffffffffu, nm, o);
            pm = pm > pp ? pm : pp;
            nm = nm < nn ? nm : nn;
        }
        if ((lane & 3) == 0) {
            int row = wr * 32 + (r4 >> 1) * 16 + (r4 & 1) * 8 + (lane >> 2);
            atomicMax(&smax_i[row], (int)pm);
            atomicMin(&smin_i[row], (int)nm);
        }
    }
    __syncthreads();
    if (tid < 128) {
        atomicMax(&g_maxpos[gi0 + tid], smax_i[tid]);
        atomicMin(&g_minneg[gi0 + tid], smin_i[tid]);
        atomicMax(&g_maxpos[gj0 + tid], smax_j[tid]);
        atomicMin(&g_minneg[gj0 + tid], smin_j[tid]);
    }
}

// -------- 4) loss: sqrt of hardest d2, relu, mean; 64 blocks --------
__global__ void loss_kernel(float* __restrict__ out) {
    int b = blockIdx.x, tid = threadIdx.x;   // 64 blocks x 128 threads
    int i = b * 128 + tid;
    float mp = sqrtf(__int_as_float(g_maxpos[i]));
    float mn = sqrtf(__int_as_float(g_minneg[i]));
    float l = mp - mn + MARGIN;
    float s = (l > 0.0f) ? l : 0.0f;
    #pragma unroll
    for (int o = 16; o > 0; o >>= 1) s += __shfl_xor_sync(0xffffffffu, s, o);
    __shared__ float warp_s[4];
    int wid = tid >> 5, lid = tid & 31;
    if (lid == 0) warp_s[wid] = s;
    __syncthreads();
    if (tid == 0) {
        float tt = warp_s[0] + warp_s[1] + warp_s[2] + warp_s[3];
        g_part[b] = tt;
        __threadfence();
        int old = atomicAdd(&g_cnt, 1);
        if (old == 63) {   // last block combines in fixed order -> deterministic
            __threadfence();
            float total = 0.0f;
            volatile float* vp = g_part;
            #pragma unroll
            for (int k = 0; k < 64; k++) total += vp[k];
            out[0] = total / (float)N;
        }
    }
}

extern "C" void kernel_launch(void* const* d_in, const int* in_sizes, int n_in,
                              void* d_out, int out_size) {
    const float* features = (const float*)d_in[0];
    const void*  labels   = d_in[1];
    (void)in_sizes; (void)n_in; (void)out_size;

    cudaFuncSetAttribute(tile_kernel,
                         cudaFuncAttributeMaxDynamicSharedMemorySize, SMEM_BYTES);

    labels_kernel<<<32, 256>>>(labels);
    normalize_convert_kernel<<<1024, 256>>>(features);
    tile_kernel<<<NTILES, 256, SMEM_BYTES>>>();
    loss_kernel<<<64, 128>>>((float*)d_out);
}

// round 11
// speedup vs baseline: 1.4290x; 1.4290x over previous
#include <cuda_runtime.h>
#include <cuda_fp16.h>
#include <math.h>
#include <stdint.h>

#define N 8192
#define D 256
#define K3 256                 // fp16-quantized embedding, exact dist on quantized vecs
#define TM 128
#define TN 128
#define NTB (N / TM)           // 64
#define NTILES (NTB * (NTB + 1) / 2)   // 2080
#define GRID_TILES 2072        // first 8 CTAs take 2 tiles -> no tail wave
#define KC 64                  // k-elems per chunk = 128B rows
#define NC (K3 / KC)           // 4
#define MARGIN 0.3f
#define POS_INF_BITS 0x7f800000

// 3-stage smem: stage = A(16KB) + B(16KB)
#define STAGE_BYTES 32768
#define OFF_STAT (3 * STAGE_BYTES)     // 98304
#define STAT_BYTES 4096
#define SMEM_BYTES (OFF_STAT + STAT_BYTES + 1024)

// -------- device scratch --------
__device__ __half g_F[(size_t)N * K3];   // fp16-quantized normalized features
__device__ float g_sq[N];                // exact ||f_hat||^2 in fp32
__device__ int   g_lab[N];
__device__ int   g_maxpos[N];   // d2 float bits (>=0 -> monotone as int); sqrt deferred
__device__ int   g_minneg[N];
__device__ float g_part[8];
__device__ int   g_cnt;

// -------- helpers --------
__device__ __forceinline__ uint32_t smem_u32(const void* p) {
    return (uint32_t)__cvta_generic_to_shared(p);
}
__device__ __forceinline__ uint32_t swz(int row, int g) {   // 128B rows, 16B groups
    return (uint32_t)(row * 128 + ((g ^ (row & 7)) << 4));
}
__device__ __forceinline__ void cp16(uint32_t saddr, const void* gaddr) {
    asm volatile("cp.async.cg.shared.global [%0], [%1], 16;"
                 :: "r"(saddr), "l"(gaddr) : "memory");
}
__device__ __forceinline__ void ldsm4(uint32_t& r0, uint32_t& r1, uint32_t& r2,
                                      uint32_t& r3, uint32_t addr) {
    asm volatile("ldmatrix.sync.aligned.m8n8.x4.shared.b16 {%0,%1,%2,%3}, [%4];"
                 : "=r"(r0), "=r"(r1), "=r"(r2), "=r"(r3) : "r"(addr));
}
__device__ __forceinline__ void mma16816(float* d, const uint32_t* a, const uint32_t* b) {
    asm volatile(
        "mma.sync.aligned.m16n8k16.row.col.f32.f16.f16.f32 "
        "{%0,%1,%2,%3}, {%4,%5,%6,%7}, {%8,%9}, {%0,%1,%2,%3};"
        : "+f"(d[0]), "+f"(d[1]), "+f"(d[2]), "+f"(d[3])
        : "r"(a[0]), "r"(a[1]), "r"(a[2]), "r"(a[3]), "r"(b[0]), "r"(b[1]));
}

// -------- 1) prep: normalize+quantize (blocks 0..N-1) | labels+init (blocks N..N+31)
__global__ void prep_kernel(const float* __restrict__ f,
                            const void* __restrict__ labels_raw) {
    int tid = threadIdx.x;           // 256 threads
    int wid = tid >> 5, lid = tid & 31;
    if (blockIdx.x < N) {
        // --- normalize row (R9-proven code) ---
        int row = blockIdx.x;
        float v = f[row * D + tid];
        float ss = v * v;
        #pragma unroll
        for (int o = 16; o > 0; o >>= 1) ss += __shfl_xor_sync(0xffffffffu, ss, o);
        __shared__ float warp_s[8];
        if (lid == 0) warp_s[wid] = ss;
        __syncthreads();
        if (wid == 0) {
            float s = (lid < 8) ? warp_s[lid] : 0.0f;
            #pragma unroll
            for (int o = 4; o > 0; o >>= 1) s += __shfl_xor_sync(0xffffffffu, s, o);
            if (lid == 0) warp_s[0] = s;
        }
        __syncthreads();
        float inv = 1.0f / fmaxf(sqrtf(warp_s[0]), 1e-12f);
        __half hq = __float2half_rn(v * inv);
        g_F[(size_t)row * K3 + tid] = hq;
        // exact squared norm of the QUANTIZED vector
        float h = __half2float(hq);
        float s2 = h * h;
        #pragma unroll
        for (int o = 16; o > 0; o >>= 1) s2 += __shfl_xor_sync(0xffffffffu, s2, o);
        __syncthreads();
        if (lid == 0) warp_s[wid] = s2;
        __syncthreads();
        if (wid == 0) {
            float s = (lid < 8) ? warp_s[lid] : 0.0f;
            #pragma unroll
            for (int o = 4; o > 0; o >>= 1) s += __shfl_xor_sync(0xffffffffu, s, o);
            if (lid == 0) g_sq[row] = s;
        }
    } else {
        // --- labels: every label-block independently samples the same first
        // 128 odd words to decide int64 vs int32 (deterministic) ---
        const int* w = (const int*)labels_raw;
        int b = blockIdx.x - N;      // 0..31
        if (b == 0 && tid == 0) g_cnt = 0;
        unsigned nz = 0;
        if (tid < 128) nz = (w[2 * tid + 1] != 0) ? 1u : 0u;
        nz = __ballot_sync(0xffffffffu, nz != 0);
        __shared__ unsigned s_nz[8];
        if (lid == 0) s_nz[wid] = nz;
        __syncthreads();
        bool is64 = ((s_nz[0] | s_nz[1] | s_nz[2] | s_nz[3]) == 0);
        int i = b * 256 + tid;
        g_lab[i] = is64 ? w[2 * i] : w[i];
        g_maxpos[i] = 0;
        g_minneg[i] = POS_INF_BITS;
    }
}

// -------- cp.async issue of one k-chunk into one smem stage --------
__device__ __forceinline__ void issue_chunk(uint32_t sb, int gi0, int gj0,
                                            int c, int tid) {
    uint32_t stage = sb + (uint32_t)(c % 3) * STAGE_BYTES;
    #pragma unroll
    for (int l = 0; l < 4; l++) {
        int idx = tid + l * 256;
        int row = idx >> 3, g = idx & 7;
        cp16(stage + swz(row, g),
             g_F + (size_t)(gi0 + row) * K3 + c * KC + g * 8);
        cp16(stage + 16384u + swz(row, g),
             g_F + (size_t)(gj0 + row) * K3 + c * KC + g * 8);
    }
}

// -------- 2) HMMA gram + fused epilogue (d2-space max/min) --------
// grid = 2072; CTAs 0..7 process a second tile (t + 2072): no tail wave.
__global__ void __launch_bounds__(256, 2) tile_kernel() {
    extern __shared__ __align__(128) char dsm[];
    uint32_t raw = smem_u32(dsm);
    uint32_t sb = (raw + 1023) & ~1023u;
    char* base = dsm + (sb - raw);

    int*   lab_i_s = (int*)(base + OFF_STAT);
    float* sq_i_s  = (float*)(base + OFF_STAT + 512);
    int*   lab_j_s = (int*)(base + OFF_STAT + 1024);
    float* sq_j_s  = (float*)(base + OFF_STAT + 1536);
    int*   smax_i  = (int*)(base + OFF_STAT + 2048);
    int*   smin_i  = (int*)(base + OFF_STAT + 2560);
    int*   smax_j  = (int*)(base + OFF_STAT + 3072);
    int*   smin_j  = (int*)(base + OFF_STAT + 3584);

    int tid = threadIdx.x;
    int wid = tid >> 5, lane = tid & 31;
    int wr = wid & 3, wc = wid >> 2;          // 4x2 warp grid: 32 rows x 64 cols
    int nrep = (blockIdx.x < NTILES - GRID_TILES) ? 2 : 1;

    for (int rep = 0; rep < nrep; rep++) {
        int t = (int)blockIdx.x + rep * GRID_TILES;
        // linear index -> (bi, bj) with bj >= bi
        int p = (int)((sqrtf(8.0f * (float)t + 1.0f) - 1.0f) * 0.5f);
        while ((p + 1) * (p + 2) / 2 <= t) p++;
        while (p * (p + 1) / 2 > t) p--;
        int bi = t - p * (p + 1) / 2;
        int bj = p;
        int gi0 = bi * TM, gj0 = bj * TN;

        // prologue: chunks 0 and 1 into stages 0,1
        issue_chunk(sb, gi0, gj0, 0, tid);
        asm volatile("cp.async.commit_group;" ::: "memory");
        issue_chunk(sb, gi0, gj0, 1, tid);
        asm volatile("cp.async.commit_group;" ::: "memory");

        if (tid < 128) {
            lab_i_s[tid] = g_lab[gi0 + tid];
            sq_i_s[tid]  = g_sq[gi0 + tid];
            lab_j_s[tid] = g_lab[gj0 + tid];
            sq_j_s[tid]  = g_sq[gj0 + tid];
            smax_i[tid] = 0; smin_i[tid] = POS_INF_BITS;
            smax_j[tid] = 0; smin_j[tid] = POS_INF_BITS;
        }

        float d[16][4];
        #pragma unroll
        for (int q = 0; q < 16; q++)
            #pragma unroll
            for (int r = 0; r < 4; r++) d[q][r] = 0.0f;

        // ldmatrix lane addressing
        int a_row = wr * 32 + ((lane >> 3) & 1) * 8 + (lane & 7);   // + mt*16
        int a_gh  = lane >> 4;
        int b_row = wc * 64 + ((lane >> 4) & 1) * 8 + (lane & 7);   // + p*16
        int b_gh  = (lane >> 3) & 1;

        uint32_t afr[2][8], bfr[2][16];

        for (int c = 0; c < NC; c++) {
            asm volatile("cp.async.wait_group 1;" ::: "memory");
            __syncthreads();
            if (c + 2 < NC) issue_chunk(sb, gi0, gj0, c + 2, tid);
            asm volatile("cp.async.commit_group;" ::: "memory");

            uint32_t abase = sb + (uint32_t)(c % 3) * STAGE_BYTES;
            uint32_t bbase = abase + 16384u;

            // preload kk=0 fragments
            ldsm4(afr[0][0], afr[0][1], afr[0][2], afr[0][3], abase + swz(a_row,      a_gh));
            ldsm4(afr[0][4], afr[0][5], afr[0][6], afr[0][7], abase + swz(a_row + 16, a_gh));
            #pragma unroll
            for (int pp = 0; pp < 4; pp++)
                ldsm4(bfr[0][4 * pp], bfr[0][4 * pp + 1], bfr[0][4 * pp + 2], bfr[0][4 * pp + 3],
                      bbase + swz(b_row + pp * 16, b_gh));

            #pragma unroll
            for (int kk = 0; kk < 4; kk++) {
                int cur = kk & 1, nxt = cur ^ 1;
                if (kk < 3) {   // prefetch kk+1 fragments before consuming kk
                    ldsm4(afr[nxt][0], afr[nxt][1], afr[nxt][2], afr[nxt][3],
                          abase + swz(a_row,      (kk + 1) * 2 + a_gh));
                    ldsm4(afr[nxt][4], afr[nxt][5], afr[nxt][6], afr[nxt][7],
                          abase + swz(a_row + 16, (kk + 1) * 2 + a_gh));
                    #pragma unroll
                    for (int pp = 0; pp < 4; pp++)
                        ldsm4(bfr[nxt][4 * pp], bfr[nxt][4 * pp + 1],
                              bfr[nxt][4 * pp + 2], bfr[nxt][4 * pp + 3],
                              bbase + swz(b_row + pp * 16, (kk + 1) * 2 + b_gh));
                }
                #pragma unroll
                for (int mt = 0; mt < 2; mt++)
                    #pragma unroll
                    for (int nt = 0; nt < 8; nt++)
                        mma16816(d[mt * 8 + nt], &afr[cur][mt * 4], &bfr[cur][nt * 2]);
            }
        }

        // ---- epilogue: masked max/min on d2 (sqrt deferred; monotone) ----
        float rmx[4], rmn[4], si[4];
        int li[4];
        #pragma unroll
        for (int mt = 0; mt < 2; mt++)
            #pragma unroll
            for (int h = 0; h < 2; h++) {
                int row = wr * 32 + mt * 16 + h * 8 + (lane >> 2);
                li[mt * 2 + h] = lab_i_s[row];
                si[mt * 2 + h] = sq_i_s[row];
                rmx[mt * 2 + h] = 0.0f;
                rmn[mt * 2 + h] = __int_as_float(POS_INF_BITS);
            }

        #pragma unroll
        for (int nt = 0; nt < 8; nt++) {
            #pragma unroll
            for (int cc = 0; cc < 2; cc++) {
                int col = wc * 64 + nt * 8 + (lane & 3) * 2 + cc;
                int lj = lab_j_s[col];
                float sj = sq_j_s[col];
                float pmax = 0.0f, nmin = __int_as_float(POS_INF_BITS);
                #pragma unroll
                for (int mt = 0; mt < 2; mt++)
                    #pragma unroll
                    for (int h = 0; h < 2; h++) {
                        float g = d[mt * 8 + nt][h * 2 + cc];
                        float d2 = fmaxf(si[mt * 2 + h] + sj - 2.0f * g, 1e-12f);
                        if (li[mt * 2 + h] == lj) {
                            rmx[mt * 2 + h] = fmaxf(rmx[mt * 2 + h], d2);
                            pmax = fmaxf(pmax, d2);
                        } else {
                            rmn[mt * 2 + h] = fminf(rmn[mt * 2 + h], d2);
                            nmin = fminf(nmin, d2);
                        }
                    }
                unsigned pm = __float_as_uint(pmax), nm = __float_as_uint(nmin);
                #pragma unroll
                for (int o = 4; o <= 16; o <<= 1) {
                    unsigned pp = __shfl_xor_sync(0xffffffffu, pm, o);
                    unsigned nn = __shfl_xor_sync(0xffffffffu, nm, o);
                    pm = pm > pp ? pm : pp;
                    nm = nm < nn ? nm : nn;
                }
                if ((lane >> 2) == 0) {
                    atomicMax(&smax_j[col], (int)pm);
                    atomicMin(&smin_j[col], (int)nm);
                }
            }
        }
        #pragma unroll
        for (int r4 = 0; r4 < 4; r4++) {
            unsigned pm = __float_as_uint(rmx[r4]), nm = __float_as_uint(rmn[r4]);
            #pragma unroll
            for (int o = 1; o <= 2; o <<= 1) {
                unsigned pp = __shfl_xor_sync(0xffffffffu, pm, o);
                unsigned nn = __shfl_xor_sync(0xffffffffu, nm, o);
                pm = pm > pp ? pm : pp;
                nm = nm < nn ? nm : nn;
            }
            if ((lane & 3) == 0) {
                int row = wr * 32 + (r4 >> 1) * 16 + (r4 & 1) * 8 + (lane >> 2);
                atomicMax(&smax_i[row], (int)pm);
                atomicMin(&smin_i[row], (int)nm);
            }
        }
        __syncthreads();
        if (tid < 128) {
            atomicMax(&g_maxpos[gi0 + tid], smax_i[tid]);
            atomicMin(&g_minneg[gi0 + tid], smin_i[tid]);
            atomicMax(&g_maxpos[gj0 + tid], smax_j[tid]);
            atomicMin(&g_minneg[gj0 + tid], smin_j[tid]);
        }
        // per-thread ordering guarantees each thread reads its own smem stats
        // above before re-initializing them in the next rep; cross-thread stat
        // reads all happen before the mainloop barriers of the next rep.
    }
}

// -------- 3) loss: sqrt of hardest d2, relu, mean; 8-block (R9-proven) ------
__global__ void loss_kernel(float* __restrict__ out) {
    int b = blockIdx.x, tid = threadIdx.x;   // 8 blocks x 1024 threads
    int i = b * 1024 + tid;
    float mp = sqrtf(__int_as_float(g_maxpos[i]));
    float mn = sqrtf(__int_as_float(g_minneg[i]));
    float l = mp - mn + MARGIN;
    float s = (l > 0.0f) ? l : 0.0f;
    #pragma unroll
    for (int o = 16; o > 0; o >>= 1) s += __shfl_xor_sync(0xffffffffu, s, o);
    __shared__ float warp_s[32];
    int wid = tid >> 5, lid = tid & 31;
    if (lid == 0) warp_s[wid] = s;
    __syncthreads();
    if (wid == 0) {
        float tt = warp_s[lid];
        #pragma unroll
        for (int o = 16; o > 0; o >>= 1) tt += __shfl_xor_sync(0xffffffffu, tt, o);
        if (lid == 0) {
            g_part[b] = tt;
            __threadfence();
            int old = atomicAdd(&g_cnt, 1);
            if (old == 7) {   // last block combines in fixed order -> deterministic
                __threadfence();
                float total = 0.0f;
                volatile float* vp = g_part;
                #pragma unroll
                for (int k = 0; k < 8; k++) total += vp[k];
                out[0] = total / (float)N;
            }
        }
    }
}

extern "C" void kernel_launch(void* const* d_in, const int* in_sizes, int n_in,
                              void* d_out, int out_size) {
    const float* features = (const float*)d_in[0];
    const void*  labels   = d_in[1];
    (void)in_sizes; (void)n_in; (void)out_size;

    cudaFuncSetAttribute(tile_kernel,
                         cudaFuncAttributeMaxDynamicSharedMemorySize, SMEM_BYTES);

    prep_kernel<<<N + 32, 256>>>(features, labels);
    tile_kernel<<<GRID_TILES, 256, SMEM_BYTES>>>();
    loss_kernel<<<8, 1024>>>((float*)d_out);
}

// round 13
// speedup vs baseline: 1.5747x; 1.1020x over previous
#include <cuda_runtime.h>
#include <cuda_fp16.h>
#include <math.h>
#include <stdint.h>

#define N 8192
#define D 256
#define K3 256                 // fp16-quantized embedding, exact dist on quantized vecs
#define TM 128
#define TN 128
#define NTB (N / TM)           // 64
#define NTILES (NTB * (NTB + 1) / 2)   // 2080
#define GRID_TILES 2072        // first 8 CTAs take 2 tiles -> no tail wave
#define KC 64                  // k-elems per chunk = 128B rows
#define NC (K3 / KC)           // 4
#define MARGIN 0.3f
#define POS_INF_BITS 0x7f800000

// 3-stage smem: stage = A(16KB) + B(16KB)
#define STAGE_BYTES 32768
#define OFF_STAT (3 * STAGE_BYTES)     // 98304
#define STAT_BYTES 4096
#define SMEM_BYTES (OFF_STAT + STAT_BYTES + 1024)

#define PREP_NORM_BLOCKS 1024          // 8 rows per block (warp-per-row)

// -------- device scratch --------
__device__ __half g_F[(size_t)N * K3];   // fp16-quantized normalized features
__device__ float g_sq[N];                // exact ||f_hat||^2 in fp32
__device__ int   g_lab[N];
__device__ int   g_maxpos[N];   // d2 float bits (>=0 -> monotone as int); sqrt deferred
__device__ int   g_minneg[N];
__device__ float g_part[8];
__device__ int   g_cnt;

// -------- helpers --------
__device__ __forceinline__ uint32_t smem_u32(const void* p) {
    return (uint32_t)__cvta_generic_to_shared(p);
}
__device__ __forceinline__ uint32_t swz(int row, int g) {   // 128B rows, 16B groups
    return (uint32_t)(row * 128 + ((g ^ (row & 7)) << 4));
}
__device__ __forceinline__ void cp16(uint32_t saddr, const void* gaddr) {
    asm volatile("cp.async.cg.shared.global [%0], [%1], 16;"
                 :: "r"(saddr), "l"(gaddr) : "memory");
}
__device__ __forceinline__ void ldsm4(uint32_t& r0, uint32_t& r1, uint32_t& r2,
                                      uint32_t& r3, uint32_t addr) {
    asm volatile("ldmatrix.sync.aligned.m8n8.x4.shared.b16 {%0,%1,%2,%3}, [%4];"
                 : "=r"(r0), "=r"(r1), "=r"(r2), "=r"(r3) : "r"(addr));
}
__device__ __forceinline__ void mma16816(float* d, const uint32_t* a, const uint32_t* b) {
    asm volatile(
        "mma.sync.aligned.m16n8k16.row.col.f32.f16.f16.f32 "
        "{%0,%1,%2,%3}, {%4,%5,%6,%7}, {%8,%9}, {%0,%1,%2,%3};"
        : "+f"(d[0]), "+f"(d[1]), "+f"(d[2]), "+f"(d[3])
        : "r"(a[0]), "r"(a[1]), "r"(a[2]), "r"(a[3]), "r"(b[0]), "r"(b[1]));
}

// -------- 1) prep: warp-per-row normalize (blocks 0..1023) | labels (blocks 1024..1055)
__global__ void prep_kernel(const float* __restrict__ f,
                            const void* __restrict__ labels_raw) {
    int tid = threadIdx.x;           // 256 threads
    int wid = tid >> 5, lid = tid & 31;
    if (blockIdx.x < PREP_NORM_BLOCKS) {
        // --- warp-per-row normalize + fp16 quantize, no block syncs ---
        int row = blockIdx.x * 8 + wid;
        const float4* fp = (const float4*)(f + (size_t)row * D);
        float4 v0 = fp[lid];          // elems [lid*4, lid*4+4)
        float4 v1 = fp[lid + 32];     // elems [128+lid*4, ...)
        float ss = v0.x * v0.x + v0.y * v0.y + v0.z * v0.z + v0.w * v0.w
                 + v1.x * v1.x + v1.y * v1.y + v1.z * v1.z + v1.w * v1.w;
        #pragma unroll
        for (int o = 16; o > 0; o >>= 1) ss += __shfl_xor_sync(0xffffffffu, ss, o);
        float inv = 1.0f / fmaxf(sqrtf(ss), 1e-12f);

        __half h0 = __float2half_rn(v0.x * inv), h1 = __float2half_rn(v0.y * inv);
        __half h2 = __float2half_rn(v0.z * inv), h3 = __float2half_rn(v0.w * inv);
        __half h4 = __float2half_rn(v1.x * inv), h5 = __float2half_rn(v1.y * inv);
        __half h6 = __float2half_rn(v1.z * inv), h7 = __float2half_rn(v1.w * inv);

        __half2* out = (__half2*)(g_F + (size_t)row * K3);
        out[lid * 2]          = __halves2half2(h0, h1);
        out[lid * 2 + 1]      = __halves2half2(h2, h3);
        out[64 + lid * 2]     = __halves2half2(h4, h5);
        out[64 + lid * 2 + 1] = __halves2half2(h6, h7);

        // exact squared norm of the QUANTIZED vector
        float q0 = __half2float(h0), q1 = __half2float(h1), q2 = __half2float(h2),
              q3 = __half2float(h3), q4 = __half2float(h4), q5 = __half2float(h5),
              q6 = __half2float(h6), q7 = __half2float(h7);
        float s2 = q0 * q0 + q1 * q1 + q2 * q2 + q3 * q3
                 + q4 * q4 + q5 * q5 + q6 * q6 + q7 * q7;
        #pragma unroll
        for (int o = 16; o > 0; o >>= 1) s2 += __shfl_xor_sync(0xffffffffu, s2, o);
        if (lid == 0) g_sq[row] = s2;
    } else {
        // --- labels: every label-block independently samples the same first
        // 128 odd words to decide int64 vs int32 (deterministic) ---
        const int* w = (const int*)labels_raw;
        int b = blockIdx.x - PREP_NORM_BLOCKS;   // 0..31
        if (b == 0 && tid == 0) g_cnt = 0;
        unsigned nz = 0;
        if (tid < 128) nz = (w[2 * tid + 1] != 0) ? 1u : 0u;
        nz = __ballot_sync(0xffffffffu, nz != 0);
        __shared__ unsigned s_nz[8];
        if (lid == 0) s_nz[wid] = nz;
        __syncthreads();
        bool is64 = ((s_nz[0] | s_nz[1] | s_nz[2] | s_nz[3]) == 0);
        int i = b * 256 + tid;
        g_lab[i] = is64 ? w[2 * i] : w[i];
        g_maxpos[i] = 0;
        g_minneg[i] = POS_INF_BITS;
    }
}

// -------- cp.async issue of one k-chunk into one smem stage --------
__device__ __forceinline__ void issue_chunk(uint32_t sb, int gi0, int gj0,
                                            int c, int tid) {
    uint32_t stage = sb + (uint32_t)(c % 3) * STAGE_BYTES;
    #pragma unroll
    for (int l = 0; l < 4; l++) {
        int idx = tid + l * 256;
        int row = idx >> 3, g = idx & 7;
        cp16(stage + swz(row, g),
             g_F + (size_t)(gi0 + row) * K3 + c * KC + g * 8);
        cp16(stage + 16384u + swz(row, g),
             g_F + (size_t)(gj0 + row) * K3 + c * KC + g * 8);
    }
}

// -------- 2) HMMA gram + fused epilogue (d2-space max/min) --------
// grid = 2072; CTAs 0..7 process a second tile (t + 2072): no tail wave.
__global__ void __launch_bounds__(256, 2) tile_kernel() {
    extern __shared__ __align__(128) char dsm[];
    uint32_t raw = smem_u32(dsm);
    uint32_t sb = (raw + 1023) & ~1023u;
    char* base = dsm + (sb - raw);

    int*   lab_i_s = (int*)(base + OFF_STAT);
    float* sq_i_s  = (float*)(base + OFF_STAT + 512);
    int*   lab_j_s = (int*)(base + OFF_STAT + 1024);
    float* sq_j_s  = (float*)(base + OFF_STAT + 1536);
    int*   smax_i  = (int*)(base + OFF_STAT + 2048);
    int*   smin_i  = (int*)(base + OFF_STAT + 2560);
    int*   smax_j  = (int*)(base + OFF_STAT + 3072);
    int*   smin_j  = (int*)(base + OFF_STAT + 3584);

    int tid = threadIdx.x;
    int wid = tid >> 5, lane = tid & 31;
    int wr = wid & 3, wc = wid >> 2;          // 4x2 warp grid: 32 rows x 64 cols
    int nrep = (blockIdx.x < NTILES - GRID_TILES) ? 2 : 1;

    for (int rep = 0; rep < nrep; rep++) {
        int t = (int)blockIdx.x + rep * GRID_TILES;
        // linear index -> (bi, bj) with bj >= bi
        int p = (int)((sqrtf(8.0f * (float)t + 1.0f) - 1.0f) * 0.5f);
        while ((p + 1) * (p + 2) / 2 <= t) p++;
        while (p * (p + 1) / 2 > t) p--;
        int bi = t - p * (p + 1) / 2;
        int bj = p;
        int gi0 = bi * TM, gj0 = bj * TN;

        // prologue: chunks 0 and 1 into stages 0,1
        issue_chunk(sb, gi0, gj0, 0, tid);
        asm volatile("cp.async.commit_group;" ::: "memory");
        issue_chunk(sb, gi0, gj0, 1, tid);
        asm volatile("cp.async.commit_group;" ::: "memory");

        if (tid < 128) {
            lab_i_s[tid] = g_lab[gi0 + tid];
            sq_i_s[tid]  = g_sq[gi0 + tid];
            lab_j_s[tid] = g_lab[gj0 + tid];
            sq_j_s[tid]  = g_sq[gj0 + tid];
            smax_i[tid] = 0; smin_i[tid] = POS_INF_BITS;
            smax_j[tid] = 0; smin_j[tid] = POS_INF_BITS;
        }

        float d[16][4];
        #pragma unroll
        for (int q = 0; q < 16; q++)
            #pragma unroll
            for (int r = 0; r < 4; r++) d[q][r] = 0.0f;

        // ldmatrix lane addressing
        int a_row = wr * 32 + ((lane >> 3) & 1) * 8 + (lane & 7);   // + mt*16
        int a_gh  = lane >> 4;
        int b_row = wc * 64 + ((lane >> 4) & 1) * 8 + (lane & 7);   // + p*16
        int b_gh  = (lane >> 3) & 1;

        uint32_t afr[2][8], bfr[2][16];

        for (int c = 0; c < NC; c++) {
            asm volatile("cp.async.wait_group 1;" ::: "memory");
            __syncthreads();
            if (c + 2 < NC) issue_chunk(sb, gi0, gj0, c + 2, tid);
            asm volatile("cp.async.commit_group;" ::: "memory");

            uint32_t abase = sb + (uint32_t)(c % 3) * STAGE_BYTES;
            uint32_t bbase = abase + 16384u;

            // preload kk=0 fragments
            ldsm4(afr[0][0], afr[0][1], afr[0][2], afr[0][3], abase + swz(a_row,      a_gh));
            ldsm4(afr[0][4], afr[0][5], afr[0][6], afr[0][7], abase + swz(a_row + 16, a_gh));
            #pragma unroll
            for (int pp = 0; pp < 4; pp++)
                ldsm4(bfr[0][4 * pp], bfr[0][4 * pp + 1], bfr[0][4 * pp + 2], bfr[0][4 * pp + 3],
                      bbase + swz(b_row + pp * 16, b_gh));

            #pragma unroll
            for (int kk = 0; kk < 4; kk++) {
                int cur = kk & 1, nxt = cur ^ 1;
                if (kk < 3) {   // prefetch kk+1 fragments before consuming kk
                    ldsm4(afr[nxt][0], afr[nxt][1], afr[nxt][2], afr[nxt][3],
                          abase + swz(a_row,      (kk + 1) * 2 + a_gh));
                    ldsm4(afr[nxt][4], afr[nxt][5], afr[nxt][6], afr[nxt][7],
                          abase + swz(a_row + 16, (kk + 1) * 2 + a_gh));
                    #pragma unroll
                    for (int pp = 0; pp < 4; pp++)
                        ldsm4(bfr[nxt][4 * pp], bfr[nxt][4 * pp + 1],
                              bfr[nxt][4 * pp + 2], bfr[nxt][4 * pp + 3],
                              bbase + swz(b_row + pp * 16, (kk + 1) * 2 + b_gh));
                }
                #pragma unroll
                for (int mt = 0; mt < 2; mt++)
                    #pragma unroll
                    for (int nt = 0; nt < 8; nt++)
                        mma16816(d[mt * 8 + nt], &afr[cur][mt * 4], &bfr[cur][nt * 2]);
            }
        }

        // ---- epilogue: masked max/min on d2 (sqrt deferred; monotone) ----
        float rmx[4], rmn[4], si[4];
        int li[4];
        #pragma unroll
        for (int mt = 0; mt < 2; mt++)
            #pragma unroll
            for (int h = 0; h < 2; h++) {
                int row = wr * 32 + mt * 16 + h * 8 + (lane >> 2);
                li[mt * 2 + h] = lab_i_s[row];
                si[mt * 2 + h] = sq_i_s[row];
                rmx[mt * 2 + h] = 0.0f;
                rmn[mt * 2 + h] = __int_as_float(POS_INF_BITS);
            }

        #pragma unroll
        for (int nt = 0; nt < 8; nt++) {
            #pragma unroll
            for (int cc = 0; cc < 2; cc++) {
                int col = wc * 64 + nt * 8 + (lane & 3) * 2 + cc;
                int lj = lab_j_s[col];
                float sj = sq_j_s[col];
                float pmax = 0.0f, nmin = __int_as_float(POS_INF_BITS);
                #pragma unroll
                for (int mt = 0; mt < 2; mt++)
                    #pragma unroll
                    for (int h = 0; h < 2; h++) {
                        float g = d[mt * 8 + nt][h * 2 + cc];
                        float d2 = fmaxf(si[mt * 2 + h] + sj - 2.0f * g, 1e-12f);
                        if (li[mt * 2 + h] == lj) {
                            rmx[mt * 2 + h] = fmaxf(rmx[mt * 2 + h], d2);
                            pmax = fmaxf(pmax, d2);
                        } else {
                            rmn[mt * 2 + h] = fminf(rmn[mt * 2 + h], d2);
                            nmin = fminf(nmin, d2);
                        }
                    }
                unsigned pm = __float_as_uint(pmax), nm = __float_as_uint(nmin);
                #pragma unroll
                for (int o = 4; o <= 16; o <<= 1) {
                    unsigned pp = __shfl_xor_sync(0xffffffffu, pm, o);
                    unsigned nn = __shfl_xor_sync(0xffffffffu, nm, o);
                    pm = pm > pp ? pm : pp;
                    nm = nm < nn ? nm : nn;
                }
                if ((lane >> 2) == 0) {
                    atomicMax(&smax_j[col], (int)pm);
                    atomicMin(&smin_j[col], (int)nm);
                }
            }
        }
        #pragma unroll
        for (int r4 = 0; r4 < 4; r4++) {
            unsigned pm = __float_as_uint(rmx[r4]), nm = __float_as_uint(rmn[r4]);
            #pragma unroll
            for (int o = 1; o <= 2; o <<= 1) {
                unsigned pp = __shfl_xor_sync(0xffffffffu, pm, o);
                unsigned nn = __shfl_xor_sync(0xffffffffu, nm, o);
                pm = pm > pp ? pm : pp;
                nm = nm < nn ? nm : nn;
            }
            if ((lane & 3) == 0) {
                int row = wr * 32 + (r4 >> 1) * 16 + (r4 & 1) * 8 + (lane >> 2);
                atomicMax(&smax_i[row], (int)pm);
                atomicMin(&smin_i[row], (int)nm);
            }
        }
        __syncthreads();
        if (tid < 128) {
            atomicMax(&g_maxpos[gi0 + tid], smax_i[tid]);
            atomicMin(&g_minneg[gi0 + tid], smin_i[tid]);
            atomicMax(&g_maxpos[gj0 + tid], smax_j[tid]);
            atomicMin(&g_minneg[gj0 + tid], smin_j[tid]);
        }
        // per-thread ordering guarantees each thread reads its own smem stats
        // above before re-initializing them in the next rep; cross-thread stat
        // reads all happen before the mainloop barriers of the next rep.
    }
}

// -------- 3) loss: sqrt of hardest d2, relu, mean; 8-block (R9-proven) ------
__global__ void loss_kernel(float* __restrict__ out) {
    int b = blockIdx.x, tid = threadIdx.x;   // 8 blocks x 1024 threads
    int i = b * 1024 + tid;
    float mp = sqrtf(__int_as_float(g_maxpos[i]));
    float mn = sqrtf(__int_as_float(g_minneg[i]));
    float l = mp - mn + MARGIN;
    float s = (l > 0.0f) ? l : 0.0f;
    #pragma unroll
    for (int o = 16; o > 0; o >>= 1) s += __shfl_xor_sync(0xffffffffu, s, o);
    __shared__ float warp_s[32];
    int wid = tid >> 5, lid = tid & 31;
    if (lid == 0) warp_s[wid] = s;
    __syncthreads();
    if (wid == 0) {
        float tt = warp_s[lid];
        #pragma unroll
        for (int o = 16; o > 0; o >>= 1) tt += __shfl_xor_sync(0xffffffffu, tt, o);
        if (lid == 0) {
            g_part[b] = tt;
            __threadfence();
            int old = atomicAdd(&g_cnt, 1);
            if (old == 7) {   // last block combines in fixed order -> deterministic
                __threadfence();
                float total = 0.0f;
                volatile float* vp = g_part;
                #pragma unroll
                for (int k = 0; k < 8; k++) total += vp[k];
                out[0] = total / (float)N;
            }
        }
    }
}

extern "C" void kernel_launch(void* const* d_in, const int* in_sizes, int n_in,
                              void* d_out, int out_size) {
    const float* features = (const float*)d_in[0];
    const void*  labels   = d_in[1];
    (void)in_sizes; (void)n_in; (void)out_size;

    cudaFuncSetAttribute(tile_kernel,
                         cudaFuncAttributeMaxDynamicSharedMemorySize, SMEM_BYTES);

    prep_kernel<<<PREP_NORM_BLOCKS + 32, 256>>>(features, labels);
    tile_kernel<<<GRID_TILES, 256, SMEM_BYTES>>>();
    loss_kernel<<<8, 1024>>>((float*)d_out);
}